// round 1
// baseline (speedup 1.0000x reference)
#include <cuda_runtime.h>
#include <math.h>

// Problem constants
#define BB 2
#define SS 2048
#define DD 768
#define HH 12
#define DK 64
// output tensor sizes (elements)
#define OUT_MAIN (2LL*2048*768)          // 3,145,728
#define ATTN_ELEMS (2LL*12*2048*2048)    // 100,663,296

// Scratch (static device arrays: allocation-free per harness rules)
__device__ float g_Q[(size_t)BB*SS*DD];
__device__ float g_K[(size_t)BB*SS*DD];
__device__ float g_V[(size_t)BB*SS*DD];
__device__ float g_ctx[(size_t)BB*SS*DD];
__device__ float g_attn[(size_t)ATTN_ELEMS];

// ---------------------------------------------------------------------------
// Generic C[M,N] = A[M,K] @ W[N,K]^T (+ bias). Tiles 64x64x16, 256 threads,
// 4x4 micro-tile per thread. M%64==0, N%64==0, K%16==0 guaranteed here.
// ---------------------------------------------------------------------------
__global__ void gemm_xwt(const float* __restrict__ A,
                         const float* __restrict__ W,
                         const float* __restrict__ bias,
                         float* __restrict__ C,
                         int M, int N, int K) {
    __shared__ float As[16][64];
    __shared__ float Ws[16][64];

    const int tid = threadIdx.x;          // 0..255
    const int bm  = blockIdx.y * 64;
    const int bn  = blockIdx.x * 64;

    const int lm = tid >> 2;              // 0..63  (row within tile)
    const int lk = (tid & 3) * 4;         // 0,4,8,12 (k quad)
    const int tx = tid & 15;              // 0..15
    const int ty = tid >> 4;              // 0..15

    float acc[4][4];
#pragma unroll
    for (int i = 0; i < 4; i++)
#pragma unroll
        for (int j = 0; j < 4; j++) acc[i][j] = 0.f;

    for (int k0 = 0; k0 < K; k0 += 16) {
        float4 av = *(const float4*)(A + (size_t)(bm + lm) * K + k0 + lk);
        float4 wv = *(const float4*)(W + (size_t)(bn + lm) * K + k0 + lk);
        As[lk + 0][lm] = av.x; As[lk + 1][lm] = av.y;
        As[lk + 2][lm] = av.z; As[lk + 3][lm] = av.w;
        Ws[lk + 0][lm] = wv.x; Ws[lk + 1][lm] = wv.y;
        Ws[lk + 2][lm] = wv.z; Ws[lk + 3][lm] = wv.w;
        __syncthreads();

#pragma unroll
        for (int kk = 0; kk < 16; kk++) {
            float a0 = As[kk][ty * 4 + 0];
            float a1 = As[kk][ty * 4 + 1];
            float a2 = As[kk][ty * 4 + 2];
            float a3 = As[kk][ty * 4 + 3];
            float b0 = Ws[kk][tx * 4 + 0];
            float b1 = Ws[kk][tx * 4 + 1];
            float b2 = Ws[kk][tx * 4 + 2];
            float b3 = Ws[kk][tx * 4 + 3];
            acc[0][0] += a0 * b0; acc[0][1] += a0 * b1; acc[0][2] += a0 * b2; acc[0][3] += a0 * b3;
            acc[1][0] += a1 * b0; acc[1][1] += a1 * b1; acc[1][2] += a1 * b2; acc[1][3] += a1 * b3;
            acc[2][0] += a2 * b0; acc[2][1] += a2 * b1; acc[2][2] += a2 * b2; acc[2][3] += a2 * b3;
            acc[3][0] += a3 * b0; acc[3][1] += a3 * b1; acc[3][2] += a3 * b2; acc[3][3] += a3 * b3;
        }
        __syncthreads();
    }

#pragma unroll
    for (int i = 0; i < 4; i++) {
        float* crow = C + (size_t)(bm + ty * 4 + i) * N + bn;
#pragma unroll
        for (int j = 0; j < 4; j++) {
            float v = acc[i][j];
            if (bias) v += bias[bn + tx * 4 + j];
            crow[tx * 4 + j] = v;
        }
    }
}

// ---------------------------------------------------------------------------
// Causal scores + softmax for one (b, h, q) row. Writes full S-length weight
// row (exact zeros beyond the diagonal, matching exp(-1e9-max)->0 in fp32).
// attn_dst == nullptr -> write to g_attn.
// ---------------------------------------------------------------------------
__global__ void attn_softmax(const float* __restrict__ Qp,
                             const float* __restrict__ Kp,
                             float* attn_dst) {
    const int q = blockIdx.x;
    const int h = blockIdx.y;
    const int b = blockIdx.z;
    const int tid = threadIdx.x;          // 256 threads

    __shared__ float qrow[DK];
    __shared__ float s[SS];
    __shared__ float red[256];

    float* attn = attn_dst ? attn_dst : g_attn;
    float* arow = attn + (((size_t)(b * HH + h) * SS) + q) * SS;

    const float* qptr = Qp + ((size_t)(b * SS + q)) * DD + h * DK;
    if (tid < DK) qrow[tid] = qptr[tid];
    __syncthreads();

    // scores for j <= q
    float lmax = -1e30f;
    for (int j = tid; j <= q; j += 256) {
        const float4* kp4 = (const float4*)(Kp + ((size_t)(b * SS + j)) * DD + h * DK);
        float acc = 0.f;
#pragma unroll
        for (int d4 = 0; d4 < DK / 4; d4++) {
            float4 kv = kp4[d4];
            acc += qrow[d4 * 4 + 0] * kv.x + qrow[d4 * 4 + 1] * kv.y +
                   qrow[d4 * 4 + 2] * kv.z + qrow[d4 * 4 + 3] * kv.w;
        }
        acc *= 0.125f;  // 1/sqrt(64)
        s[j] = acc;
        lmax = fmaxf(lmax, acc);
    }

    // block max
    red[tid] = lmax;
    __syncthreads();
    for (int st = 128; st > 0; st >>= 1) {
        if (tid < st) red[tid] = fmaxf(red[tid], red[tid + st]);
        __syncthreads();
    }
    const float m = red[0];
    __syncthreads();

    // exp + block sum
    float lsum = 0.f;
    for (int j = tid; j <= q; j += 256) {
        float e = expf(s[j] - m);
        s[j] = e;
        lsum += e;
    }
    red[tid] = lsum;
    __syncthreads();
    for (int st = 128; st > 0; st >>= 1) {
        if (tid < st) red[tid] += red[tid + st];
        __syncthreads();
    }
    const float inv = 1.0f / red[0];
    __syncthreads();

    for (int j = tid; j <= q; j += 256) arow[j] = s[j] * inv;
    for (int j = q + 1 + tid; j < SS; j += 256) arow[j] = 0.f;
}

// ---------------------------------------------------------------------------
// ctx[b,q,h,:] = sum_j attn[b,h,q,j] * V[b,j,h,:]
// Block: 32 q-rows x 64 d, 256 threads. Causal-truncated j loop.
// ---------------------------------------------------------------------------
__global__ void attn_v(const float* attn_src,
                       const float* __restrict__ Vp,
                       float* __restrict__ ctx) {
    const int qt = blockIdx.x;            // 0..63 (tile of 32 q rows)
    const int h  = blockIdx.y;
    const int b  = blockIdx.z;
    const int q0 = qt * 32;
    const int tid = threadIdx.x;          // 256

    const float* attn = attn_src ? attn_src : g_attn;

    __shared__ float ws[32][64];
    __shared__ float vs[64][64];

    const int d  = tid & 63;              // 0..63
    const int ry = tid >> 6;              // 0..3, each handles 8 rows
    float acc[8];
#pragma unroll
    for (int i = 0; i < 8; i++) acc[i] = 0.f;

    const float* abase = attn + ((size_t)(b * HH + h) * SS) * SS;

    for (int j0 = 0; j0 < q0 + 32; j0 += 64) {
        // load 32x64 attn tile
#pragma unroll
        for (int k = 0; k < 8; k++) {
            int idx = tid + k * 256;
            int r = idx >> 6, c = idx & 63;
            ws[r][c] = abase[(size_t)(q0 + r) * SS + j0 + c];
        }
        // load 64x64 V tile
#pragma unroll
        for (int k = 0; k < 16; k++) {
            int idx = tid + k * 256;
            int r = idx >> 6, c = idx & 63;
            vs[r][c] = Vp[(size_t)(b * SS + j0 + r) * DD + h * DK + c];
        }
        __syncthreads();

#pragma unroll 8
        for (int jj = 0; jj < 64; jj++) {
            float v = vs[jj][d];
#pragma unroll
            for (int i = 0; i < 8; i++) acc[i] += ws[ry * 8 + i][jj] * v;
        }
        __syncthreads();
    }

#pragma unroll
    for (int i = 0; i < 8; i++) {
        ctx[(size_t)(b * SS + q0 + ry * 8 + i) * DD + h * DK + d] = acc[i];
    }
}

// ---------------------------------------------------------------------------
extern "C" void kernel_launch(void* const* d_in, const int* in_sizes, int n_in,
                              void* d_out, int out_size) {
    const float* q_in = (const float*)d_in[0];
    const float* k_in = (const float*)d_in[1];
    const float* v_in = (const float*)d_in[2];
    // d_in[3] = mask (int32) — causal, known statically, ignored
    const float* Wq = (const float*)d_in[4];
    const float* Wk = (const float*)d_in[5];
    const float* Wv = (const float*)d_in[6];
    const float* Wo = (const float*)d_in[7];
    const float* bo = (const float*)d_in[8];

    float* out = (float*)d_out;
    float* attn_dst = nullptr;  // nullptr -> kernels use g_attn scratch
    if ((long long)out_size >= OUT_MAIN + ATTN_ELEMS) attn_dst = out + OUT_MAIN;

    float *pQ, *pK, *pV, *pCtx;
    cudaGetSymbolAddress((void**)&pQ,   g_Q);
    cudaGetSymbolAddress((void**)&pK,   g_K);
    cudaGetSymbolAddress((void**)&pV,   g_V);
    cudaGetSymbolAddress((void**)&pCtx, g_ctx);

    const int M = BB * SS;  // 4096

    // Projections: X @ W^T
    dim3 gproj(DD / 64, M / 64);
    gemm_xwt<<<gproj, 256>>>(q_in, Wq, nullptr, pQ, M, DD, DD);
    gemm_xwt<<<gproj, 256>>>(k_in, Wk, nullptr, pK, M, DD, DD);
    gemm_xwt<<<gproj, 256>>>(v_in, Wv, nullptr, pV, M, DD, DD);

    // Causal softmax attention weights
    dim3 gattn(SS, HH, BB);
    attn_softmax<<<gattn, 256>>>(pQ, pK, attn_dst);

    // ctx = attn @ V
    dim3 gav(SS / 32, HH, BB);
    attn_v<<<gav, 256>>>(attn_dst, pV, pCtx);

    // Output projection + bias
    gemm_xwt<<<gproj, 256>>>(pCtx, Wo, bo, out, M, DD, DD);
}

// round 2
// speedup vs baseline: 3.0791x; 3.0791x over previous
#include <cuda_runtime.h>
#include <math.h>

// Problem constants
#define BB 2
#define SS 2048
#define DD 768
#define HH 12
#define DK 64
#define QROWS 16
#define S_STRIDE 2064      // padded row stride for score buffer
#define KV_STRIDE 65       // padded row stride for K/V/Q tiles

#define OUT_MAIN (2LL*2048*768)          // 3,145,728
#define ATTN_ELEMS (2LL*12*2048*2048)    // 100,663,296

// Scratch (static device arrays: allocation-free per harness rules)
__device__ float g_Q[(size_t)BB*SS*DD];
__device__ float g_K[(size_t)BB*SS*DD];
__device__ float g_V[(size_t)BB*SS*DD];
__device__ float g_ctx[(size_t)BB*SS*DD];
__device__ float g_attn[(size_t)ATTN_ELEMS];

// ---------------------------------------------------------------------------
// 128x128x8 SGEMM: C[M,N] = A[M,K] @ W[N,K]^T (+ optional bias).
// 256 threads, 8x8 micro-tile, float4 smem loads, global prefetch.
// M%128==0, N%128==0, K%8==0.
// ---------------------------------------------------------------------------
__device__ __forceinline__ void gemm128_body(const float* __restrict__ A,
                                             const float* __restrict__ W,
                                             const float* __restrict__ bias,
                                             float* __restrict__ C,
                                             int M, int N, int K,
                                             int bm, int bn) {
    __shared__ float As[8][128];
    __shared__ float Ws[8][128];

    const int tid = threadIdx.x;
    const int tx = tid & 15;
    const int ty = tid >> 4;
    const int lrow = tid >> 1;          // 0..127
    const int lk   = (tid & 1) * 4;     // 0 or 4

    const float* Aptr = A + (size_t)(bm + lrow) * K + lk;
    const float* Wptr = W + (size_t)(bn + lrow) * K + lk;

    float acc[8][8];
#pragma unroll
    for (int i = 0; i < 8; i++)
#pragma unroll
        for (int j = 0; j < 8; j++) acc[i][j] = 0.f;

    float4 a4 = *(const float4*)(Aptr);
    float4 w4 = *(const float4*)(Wptr);

    for (int k0 = 0; k0 < K; k0 += 8) {
        As[lk+0][lrow] = a4.x; As[lk+1][lrow] = a4.y;
        As[lk+2][lrow] = a4.z; As[lk+3][lrow] = a4.w;
        Ws[lk+0][lrow] = w4.x; Ws[lk+1][lrow] = w4.y;
        Ws[lk+2][lrow] = w4.z; Ws[lk+3][lrow] = w4.w;
        __syncthreads();

        if (k0 + 8 < K) {
            a4 = *(const float4*)(Aptr + k0 + 8);
            w4 = *(const float4*)(Wptr + k0 + 8);
        }

#pragma unroll
        for (int kk = 0; kk < 8; kk++) {
            float ar[8], wr[8];
            *(float4*)(ar)     = *(const float4*)&As[kk][ty*8];
            *(float4*)(ar + 4) = *(const float4*)&As[kk][ty*8 + 4];
            *(float4*)(wr)     = *(const float4*)&Ws[kk][tx*8];
            *(float4*)(wr + 4) = *(const float4*)&Ws[kk][tx*8 + 4];
#pragma unroll
            for (int i = 0; i < 8; i++)
#pragma unroll
                for (int j = 0; j < 8; j++) acc[i][j] += ar[i] * wr[j];
        }
        __syncthreads();
    }

#pragma unroll
    for (int i = 0; i < 8; i++) {
        float* crow = C + (size_t)(bm + ty*8 + i) * N + bn + tx*8;
        float4 v0, v1;
        v0.x = acc[i][0]; v0.y = acc[i][1]; v0.z = acc[i][2]; v0.w = acc[i][3];
        v1.x = acc[i][4]; v1.y = acc[i][5]; v1.z = acc[i][6]; v1.w = acc[i][7];
        if (bias) {
            const float* bp = bias + bn + tx*8;
            v0.x += bp[0]; v0.y += bp[1]; v0.z += bp[2]; v0.w += bp[3];
            v1.x += bp[4]; v1.y += bp[5]; v1.z += bp[6]; v1.w += bp[7];
        }
        *(float4*)(crow)     = v0;
        *(float4*)(crow + 4) = v1;
    }
}

// Fused Q/K/V projections: blockIdx.z selects which projection.
__global__ __launch_bounds__(256) void qkv_proj(
        const float* __restrict__ qin, const float* __restrict__ kin,
        const float* __restrict__ vin,
        const float* __restrict__ Wq, const float* __restrict__ Wk,
        const float* __restrict__ Wv,
        float* __restrict__ oq, float* __restrict__ ok, float* __restrict__ ov) {
    const float* A; const float* W; float* C;
    if (blockIdx.z == 0)      { A = qin; W = Wq; C = oq; }
    else if (blockIdx.z == 1) { A = kin; W = Wk; C = ok; }
    else                      { A = vin; W = Wv; C = ov; }
    gemm128_body(A, W, nullptr, C, BB*SS, DD, DD, blockIdx.y*128, blockIdx.x*128);
}

__global__ __launch_bounds__(256) void out_proj(
        const float* __restrict__ A, const float* __restrict__ W,
        const float* __restrict__ bias, float* __restrict__ C) {
    gemm128_body(A, W, bias, C, BB*SS, DD, DD, blockIdx.y*128, blockIdx.x*128);
}

// ---------------------------------------------------------------------------
// Fused attention: per block handles (b, h, 16 query rows).
// Keeps the full score row strip (16 x <=2048) in SMEM.
//   Phase 1: QK^T tiled (64-wide K tiles in SMEM)
//   Phase 2: row max, exp, sum (in SMEM)
//   Phase 3: write normalized weights once (coalesced)
//   Phase 4: attn @ V from SMEM scores
// ---------------------------------------------------------------------------
__global__ __launch_bounds__(256) void fused_attn(
        const float* __restrict__ Qp, const float* __restrict__ Kp,
        const float* __restrict__ Vp,
        float* __restrict__ attn, float* __restrict__ ctx) {
    // biggest blocks first (reverse qt) to avoid long tail
    const int qt = gridDim.x - 1 - blockIdx.x;
    const int h  = blockIdx.y;
    const int b  = blockIdx.z;
    const int q0 = qt * QROWS;
    const int tid = threadIdx.x;

    extern __shared__ float sm[];
    float* s    = sm;                           // [16][S_STRIDE]
    float* kv   = sm + QROWS * S_STRIDE;        // [64][KV_STRIDE]
    float* qs   = kv + 64 * KV_STRIDE;          // [16][KV_STRIDE]
    float* lrow = qs + QROWS * KV_STRIDE;       // [16] (1/sum)

    const int cg = tid & 63;   // column within tile / head dim
    const int rg = tid >> 6;   // 0..3 -> rows rg*4 .. rg*4+3

    // Load Q tile (16 x 64)
    for (int l = tid; l < QROWS * 64; l += 256) {
        int r = l >> 6, k = l & 63;
        qs[r * KV_STRIDE + k] = Qp[((size_t)(b * SS + q0 + r)) * DD + h * DK + k];
    }

    const int ntile = (q0 + QROWS + 63) >> 6;
    const int jlim  = ntile * 64;

    // ---- Phase 1: scores ----
    for (int t = 0; t < ntile; t++) {
        const int j0 = t * 64;
        __syncthreads();   // protects kv reuse + first-iter Q tile
        for (int l = tid; l < 64 * 64; l += 256) {
            int jr = l >> 6, k = l & 63;
            kv[jr * KV_STRIDE + k] =
                Kp[((size_t)(b * SS + j0 + jr)) * DD + h * DK + k];
        }
        __syncthreads();

        float a0 = 0.f, a1 = 0.f, a2 = 0.f, a3 = 0.f;
        const float* kvc = kv + cg * KV_STRIDE;
        const float* q0p = qs + (rg*4 + 0) * KV_STRIDE;
        const float* q1p = qs + (rg*4 + 1) * KV_STRIDE;
        const float* q2p = qs + (rg*4 + 2) * KV_STRIDE;
        const float* q3p = qs + (rg*4 + 3) * KV_STRIDE;
#pragma unroll 16
        for (int k = 0; k < 64; k++) {
            float kx = kvc[k];
            a0 += q0p[k] * kx;
            a1 += q1p[k] * kx;
            a2 += q2p[k] * kx;
            a3 += q3p[k] * kx;
        }
        const int gj = j0 + cg;
        s[(rg*4 + 0) * S_STRIDE + gj] = (gj <= q0 + rg*4 + 0) ? a0 * 0.125f : -1e30f;
        s[(rg*4 + 1) * S_STRIDE + gj] = (gj <= q0 + rg*4 + 1) ? a1 * 0.125f : -1e30f;
        s[(rg*4 + 2) * S_STRIDE + gj] = (gj <= q0 + rg*4 + 2) ? a2 * 0.125f : -1e30f;
        s[(rg*4 + 3) * S_STRIDE + gj] = (gj <= q0 + rg*4 + 3) ? a3 * 0.125f : -1e30f;
    }
    __syncthreads();

    // ---- Phase 2: softmax stats (16 threads per row) ----
    {
        const int r   = tid >> 4;
        const int t16 = tid & 15;
        float* srow = s + r * S_STRIDE;
        float m = -1e30f;
        for (int j = t16; j < jlim; j += 16) m = fmaxf(m, srow[j]);
#pragma unroll
        for (int o = 8; o; o >>= 1)
            m = fmaxf(m, __shfl_xor_sync(0xffffffffu, m, o, 16));
        float sum = 0.f;
        for (int j = t16; j < jlim; j += 16) {
            float e = __expf(srow[j] - m);
            srow[j] = e;
            sum += e;
        }
#pragma unroll
        for (int o = 8; o; o >>= 1)
            sum += __shfl_xor_sync(0xffffffffu, sum, o, 16);
        if (t16 == 0) lrow[r] = 1.0f / sum;
    }
    __syncthreads();

    // ---- Phase 3: write normalized weights once (coalesced) ----
    for (int r = 0; r < QROWS; r++) {
        const float inv = lrow[r];
        const float* srow = s + r * S_STRIDE;
        float* arow = attn + (((size_t)(b * HH + h) * SS) + q0 + r) * SS;
        for (int j = tid; j < jlim; j += 256) arow[j] = srow[j] * inv;
        for (int j = jlim + tid; j < SS; j += 256) arow[j] = 0.f;
    }

    // ---- Phase 4: attn @ V ----
    float c0 = 0.f, c1 = 0.f, c2 = 0.f, c3 = 0.f;
    for (int t = 0; t < ntile; t++) {
        const int j0 = t * 64;
        __syncthreads();
        for (int l = tid; l < 64 * 64; l += 256) {
            int jr = l >> 6, d = l & 63;
            kv[jr * KV_STRIDE + d] =
                Vp[((size_t)(b * SS + j0 + jr)) * DD + h * DK + d];
        }
        __syncthreads();

        const float* s0 = s + (rg*4 + 0) * S_STRIDE + j0;
        const float* s1 = s + (rg*4 + 1) * S_STRIDE + j0;
        const float* s2 = s + (rg*4 + 2) * S_STRIDE + j0;
        const float* s3 = s + (rg*4 + 3) * S_STRIDE + j0;
#pragma unroll 16
        for (int jj = 0; jj < 64; jj++) {
            float v = kv[jj * KV_STRIDE + cg];
            c0 += s0[jj] * v;
            c1 += s1[jj] * v;
            c2 += s2[jj] * v;
            c3 += s3[jj] * v;
        }
    }

    float* cbase = ctx + ((size_t)(b * SS + q0)) * DD + h * DK + cg;
    cbase[(rg*4 + 0) * (size_t)DD] = c0 * lrow[rg*4 + 0];
    cbase[(rg*4 + 1) * (size_t)DD] = c1 * lrow[rg*4 + 1];
    cbase[(rg*4 + 2) * (size_t)DD] = c2 * lrow[rg*4 + 2];
    cbase[(rg*4 + 3) * (size_t)DD] = c3 * lrow[rg*4 + 3];
}

// ---------------------------------------------------------------------------
extern "C" void kernel_launch(void* const* d_in, const int* in_sizes, int n_in,
                              void* d_out, int out_size) {
    const float* q_in = (const float*)d_in[0];
    const float* k_in = (const float*)d_in[1];
    const float* v_in = (const float*)d_in[2];
    // d_in[3] = mask (int32) — causal, known statically, ignored
    const float* Wq = (const float*)d_in[4];
    const float* Wk = (const float*)d_in[5];
    const float* Wv = (const float*)d_in[6];
    const float* Wo = (const float*)d_in[7];
    const float* bo = (const float*)d_in[8];

    float* out = (float*)d_out;
    float* attn_dst;
    if ((long long)out_size >= OUT_MAIN + ATTN_ELEMS) {
        attn_dst = out + OUT_MAIN;
    } else {
        cudaGetSymbolAddress((void**)&attn_dst, g_attn);
    }

    float *pQ, *pK, *pV, *pCtx;
    cudaGetSymbolAddress((void**)&pQ,   g_Q);
    cudaGetSymbolAddress((void**)&pK,   g_K);
    cudaGetSymbolAddress((void**)&pV,   g_V);
    cudaGetSymbolAddress((void**)&pCtx, g_ctx);

    // Fused QKV projections: grid (N/128, M/128, 3)
    dim3 gqkv(DD / 128, (BB * SS) / 128, 3);
    qkv_proj<<<gqkv, 256>>>(q_in, k_in, v_in, Wq, Wk, Wv, pQ, pK, pV);

    // Fused attention
    const int smem_bytes =
        (QROWS * S_STRIDE + 64 * KV_STRIDE + QROWS * KV_STRIDE + 16) * 4;
    cudaFuncSetAttribute(fused_attn, cudaFuncAttributeMaxDynamicSharedMemorySize,
                         smem_bytes);
    dim3 gattn(SS / QROWS, HH, BB);
    fused_attn<<<gattn, 256, smem_bytes>>>(pQ, pK, pV, attn_dst, pCtx);

    // Output projection + bias
    dim3 gout(DD / 128, (BB * SS) / 128);
    out_proj<<<gout, 256>>>(pCtx, Wo, bo, out);
}

// round 3
// speedup vs baseline: 4.9463x; 1.6064x over previous
#include <cuda_runtime.h>
#include <math.h>

// Problem constants
#define BB 2
#define SS 2048
#define DD 768
#define HH 12
#define DK 64
#define QROWS 16
#define JTILE 256
#define S_STRIDE 2064      // padded row stride for score buffer (16B aligned)
#define KV_STRIDE 65       // padded row stride for K/V tiles (conflict-free)
#define QS_STRIDE 68       // padded row stride for Q tile (16B aligned)

#define OUT_MAIN (2LL*2048*768)          // 3,145,728
#define ATTN_ELEMS (2LL*12*2048*2048)    // 100,663,296

// Scratch (static device arrays: allocation-free per harness rules)
__device__ float g_Q[(size_t)BB*SS*DD];
__device__ float g_K[(size_t)BB*SS*DD];
__device__ float g_V[(size_t)BB*SS*DD];
__device__ float g_ctx[(size_t)BB*SS*DD];
__device__ float g_attn[(size_t)ATTN_ELEMS];

// ---------------------------------------------------------------------------
// 128x128x8 SGEMM: C[M,N] = A[M,K] @ W[N,K]^T (+ optional bias).
// ---------------------------------------------------------------------------
__device__ __forceinline__ void gemm128_body(const float* __restrict__ A,
                                             const float* __restrict__ W,
                                             const float* __restrict__ bias,
                                             float* __restrict__ C,
                                             int M, int N, int K,
                                             int bm, int bn) {
    __shared__ float As[8][128];
    __shared__ float Ws[8][128];

    const int tid = threadIdx.x;
    const int tx = tid & 15;
    const int ty = tid >> 4;
    const int lrow = tid >> 1;          // 0..127
    const int lk   = (tid & 1) * 4;     // 0 or 4

    const float* Aptr = A + (size_t)(bm + lrow) * K + lk;
    const float* Wptr = W + (size_t)(bn + lrow) * K + lk;

    float acc[8][8];
#pragma unroll
    for (int i = 0; i < 8; i++)
#pragma unroll
        for (int j = 0; j < 8; j++) acc[i][j] = 0.f;

    float4 a4 = *(const float4*)(Aptr);
    float4 w4 = *(const float4*)(Wptr);

    for (int k0 = 0; k0 < K; k0 += 8) {
        As[lk+0][lrow] = a4.x; As[lk+1][lrow] = a4.y;
        As[lk+2][lrow] = a4.z; As[lk+3][lrow] = a4.w;
        Ws[lk+0][lrow] = w4.x; Ws[lk+1][lrow] = w4.y;
        Ws[lk+2][lrow] = w4.z; Ws[lk+3][lrow] = w4.w;
        __syncthreads();

        if (k0 + 8 < K) {
            a4 = *(const float4*)(Aptr + k0 + 8);
            w4 = *(const float4*)(Wptr + k0 + 8);
        }

#pragma unroll
        for (int kk = 0; kk < 8; kk++) {
            float ar[8], wr[8];
            *(float4*)(ar)     = *(const float4*)&As[kk][ty*8];
            *(float4*)(ar + 4) = *(const float4*)&As[kk][ty*8 + 4];
            *(float4*)(wr)     = *(const float4*)&Ws[kk][tx*8];
            *(float4*)(wr + 4) = *(const float4*)&Ws[kk][tx*8 + 4];
#pragma unroll
            for (int i = 0; i < 8; i++)
#pragma unroll
                for (int j = 0; j < 8; j++) acc[i][j] += ar[i] * wr[j];
        }
        __syncthreads();
    }

#pragma unroll
    for (int i = 0; i < 8; i++) {
        float* crow = C + (size_t)(bm + ty*8 + i) * N + bn + tx*8;
        float4 v0, v1;
        v0.x = acc[i][0]; v0.y = acc[i][1]; v0.z = acc[i][2]; v0.w = acc[i][3];
        v1.x = acc[i][4]; v1.y = acc[i][5]; v1.z = acc[i][6]; v1.w = acc[i][7];
        if (bias) {
            const float* bp = bias + bn + tx*8;
            v0.x += bp[0]; v0.y += bp[1]; v0.z += bp[2]; v0.w += bp[3];
            v1.x += bp[4]; v1.y += bp[5]; v1.z += bp[6]; v1.w += bp[7];
        }
        *(float4*)(crow)     = v0;
        *(float4*)(crow + 4) = v1;
    }
}

__global__ __launch_bounds__(256) void qkv_proj(
        const float* __restrict__ qin, const float* __restrict__ kin,
        const float* __restrict__ vin,
        const float* __restrict__ Wq, const float* __restrict__ Wk,
        const float* __restrict__ Wv,
        float* __restrict__ oq, float* __restrict__ ok, float* __restrict__ ov) {
    const float* A; const float* W; float* C;
    if (blockIdx.z == 0)      { A = qin; W = Wq; C = oq; }
    else if (blockIdx.z == 1) { A = kin; W = Wk; C = ok; }
    else                      { A = vin; W = Wv; C = ov; }
    gemm128_body(A, W, nullptr, C, BB*SS, DD, DD, blockIdx.y*128, blockIdx.x*128);
}

__global__ __launch_bounds__(256) void out_proj(
        const float* __restrict__ A, const float* __restrict__ W,
        const float* __restrict__ bias, float* __restrict__ C) {
    gemm128_body(A, W, bias, C, BB*SS, DD, DD, blockIdx.y*128, blockIdx.x*128);
}

// ---------------------------------------------------------------------------
// Fused attention, register-blocked.
// Block = (b, h, 16 q rows). Score strip 16 x <=2048 lives in SMEM.
//  Phase 1: QK^T, 256-wide j tiles, 4q x 4j per thread (j strided by 64)
//  Phase 2: row max/exp/sum
//  Phase 3: single coalesced weight write
//  Phase 4: attn@V, 256-wide j tiles split across 4 thread groups, 4q x 4d,
//           SMEM reduction at the end (reuses score buffer).
// ---------------------------------------------------------------------------
__global__ __launch_bounds__(256) void fused_attn(
        const float* __restrict__ Qp, const float* __restrict__ Kp,
        const float* __restrict__ Vp,
        float* __restrict__ attn, float* __restrict__ ctx) {
    const int qt = gridDim.x - 1 - blockIdx.x;   // biggest blocks first
    const int h  = blockIdx.y;
    const int b  = blockIdx.z;
    const int q0 = qt * QROWS;
    const int tid = threadIdx.x;

    extern __shared__ float sm[];
    float* s    = sm;                               // [16][S_STRIDE]
    float* kv   = sm + QROWS * S_STRIDE;            // [256][KV_STRIDE]
    float* qs   = kv + JTILE * KV_STRIDE;           // [16][QS_STRIDE]
    float* lrow = qs + QROWS * QS_STRIDE;           // [16]

    // Load Q tile (16 x 64)
    for (int l = tid; l < QROWS * 64; l += 256) {
        int r = l >> 6, k = l & 63;
        qs[r * QS_STRIDE + k] = Qp[((size_t)(b * SS + q0 + r)) * DD + h * DK + k];
    }

    const int ntile = (q0 + QROWS + JTILE - 1) >> 8;
    const int jlim  = ntile * JTILE;

    // ---- Phase 1: scores (QK^T) ----
    {
        const int tq = tid >> 6;     // q rows tq*4 .. tq*4+3
        const int tj = tid & 63;     // j cols tj + 64*m
        for (int t = 0; t < ntile; t++) {
            const int j0 = t * JTILE;
            __syncthreads();
            // load K tile 256 x 64
            for (int l = tid; l < JTILE * 16; l += 256) {
                int jr = l >> 4, k4 = (l & 15) * 4;
                float4 g = *(const float4*)(Kp +
                    ((size_t)(b * SS + j0 + jr)) * DD + h * DK + k4);
                float* dst = kv + jr * KV_STRIDE + k4;
                dst[0] = g.x; dst[1] = g.y; dst[2] = g.z; dst[3] = g.w;
            }
            __syncthreads();

            float acc[4][4];
#pragma unroll
            for (int i = 0; i < 4; i++)
#pragma unroll
                for (int m = 0; m < 4; m++) acc[i][m] = 0.f;

#pragma unroll 4
            for (int k = 0; k < 64; k += 4) {
                float4 qv[4];
#pragma unroll
                for (int i = 0; i < 4; i++)
                    qv[i] = *(const float4*)&qs[(tq*4 + i) * QS_STRIDE + k];
#pragma unroll
                for (int m = 0; m < 4; m++) {
                    const float* kp = kv + (tj + 64*m) * KV_STRIDE + k;
                    float k0v = kp[0], k1v = kp[1], k2v = kp[2], k3v = kp[3];
#pragma unroll
                    for (int i = 0; i < 4; i++)
                        acc[i][m] += qv[i].x*k0v + qv[i].y*k1v +
                                     qv[i].z*k2v + qv[i].w*k3v;
                }
            }

#pragma unroll
            for (int m = 0; m < 4; m++) {
                const int gj = j0 + tj + 64*m;
#pragma unroll
                for (int i = 0; i < 4; i++) {
                    const int qrow = q0 + tq*4 + i;
                    s[(tq*4 + i) * S_STRIDE + gj] =
                        (gj <= qrow) ? acc[i][m] * 0.125f : -1e30f;
                }
            }
        }
    }
    __syncthreads();

    // ---- Phase 2: softmax stats (16 threads per row) ----
    {
        const int r   = tid >> 4;
        const int t16 = tid & 15;
        float* srow = s + r * S_STRIDE;
        float m = -1e30f;
        for (int j = t16; j < jlim; j += 16) m = fmaxf(m, srow[j]);
#pragma unroll
        for (int o = 8; o; o >>= 1)
            m = fmaxf(m, __shfl_xor_sync(0xffffffffu, m, o, 16));
        float sum = 0.f;
        for (int j = t16; j < jlim; j += 16) {
            float e = __expf(srow[j] - m);
            srow[j] = e;
            sum += e;
        }
#pragma unroll
        for (int o = 8; o; o >>= 1)
            sum += __shfl_xor_sync(0xffffffffu, sum, o, 16);
        if (t16 == 0) lrow[r] = 1.0f / sum;
    }
    __syncthreads();

    // ---- Phase 3: write normalized weights once ----
    for (int r = 0; r < QROWS; r++) {
        const float inv = lrow[r];
        const float* srow = s + r * S_STRIDE;
        float* arow = attn + (((size_t)(b * HH + h) * SS) + q0 + r) * SS;
        for (int j = tid; j < jlim; j += 256) arow[j] = srow[j] * inv;
        for (int j = jlim + tid; j < SS; j += 256) arow[j] = 0.f;
    }

    // ---- Phase 4: attn @ V (split-j, 4q x 4d per thread) ----
    {
        const int td  = tid & 15;         // d cols td + 16*m
        const int tq4 = (tid >> 4) & 3;   // q rows tq4*4 + i
        const int tj4 = tid >> 6;         // j slice tj4*64 .. +63

        float c[4][4];
#pragma unroll
        for (int i = 0; i < 4; i++)
#pragma unroll
            for (int m = 0; m < 4; m++) c[i][m] = 0.f;

        for (int t = 0; t < ntile; t++) {
            const int j0 = t * JTILE;
            __syncthreads();
            for (int l = tid; l < JTILE * 16; l += 256) {
                int jr = l >> 4, k4 = (l & 15) * 4;
                float4 g = *(const float4*)(Vp +
                    ((size_t)(b * SS + j0 + jr)) * DD + h * DK + k4);
                float* dst = kv + jr * KV_STRIDE + k4;
                dst[0] = g.x; dst[1] = g.y; dst[2] = g.z; dst[3] = g.w;
            }
            __syncthreads();

#pragma unroll 4
            for (int jj = 0; jj < 64; jj += 4) {
                const int j = tj4 * 64 + jj;
                float4 sv[4];
#pragma unroll
                for (int i = 0; i < 4; i++)
                    sv[i] = *(const float4*)&s[(tq4*4 + i) * S_STRIDE + j0 + j];
#pragma unroll
                for (int m = 0; m < 4; m++) {
                    const int d = td + 16*m;
                    float v0 = kv[(j+0) * KV_STRIDE + d];
                    float v1 = kv[(j+1) * KV_STRIDE + d];
                    float v2 = kv[(j+2) * KV_STRIDE + d];
                    float v3 = kv[(j+3) * KV_STRIDE + d];
#pragma unroll
                    for (int i = 0; i < 4; i++)
                        c[i][m] += sv[i].x*v0 + sv[i].y*v1 +
                                   sv[i].z*v2 + sv[i].w*v3;
                }
            }
        }

        // reduce across the 4 j-slices via SMEM (reuse score buffer)
        __syncthreads();
        float* red = s;   // [4][16][64]
#pragma unroll
        for (int i = 0; i < 4; i++)
#pragma unroll
            for (int m = 0; m < 4; m++)
                red[tj4 * 1024 + (tq4*4 + i) * 64 + td + 16*m] = c[i][m];
        __syncthreads();

        for (int l = tid; l < 1024; l += 256) {
            const int q = l >> 6, d = l & 63;
            float v = red[l] + red[1024 + l] + red[2048 + l] + red[3072 + l];
            ctx[((size_t)(b * SS + q0 + q)) * DD + h * DK + d] = v * lrow[q];
        }
    }
}

// ---------------------------------------------------------------------------
extern "C" void kernel_launch(void* const* d_in, const int* in_sizes, int n_in,
                              void* d_out, int out_size) {
    const float* q_in = (const float*)d_in[0];
    const float* k_in = (const float*)d_in[1];
    const float* v_in = (const float*)d_in[2];
    // d_in[3] = mask (int32) — causal, known statically, ignored
    const float* Wq = (const float*)d_in[4];
    const float* Wk = (const float*)d_in[5];
    const float* Wv = (const float*)d_in[6];
    const float* Wo = (const float*)d_in[7];
    const float* bo = (const float*)d_in[8];

    float* out = (float*)d_out;
    float* attn_dst;
    if ((long long)out_size >= OUT_MAIN + ATTN_ELEMS) {
        attn_dst = out + OUT_MAIN;
    } else {
        cudaGetSymbolAddress((void**)&attn_dst, g_attn);
    }

    float *pQ, *pK, *pV, *pCtx;
    cudaGetSymbolAddress((void**)&pQ,   g_Q);
    cudaGetSymbolAddress((void**)&pK,   g_K);
    cudaGetSymbolAddress((void**)&pV,   g_V);
    cudaGetSymbolAddress((void**)&pCtx, g_ctx);

    // Fused QKV projections
    dim3 gqkv(DD / 128, (BB * SS) / 128, 3);
    qkv_proj<<<gqkv, 256>>>(q_in, k_in, v_in, Wq, Wk, Wv, pQ, pK, pV);

    // Fused attention
    const int smem_bytes =
        (QROWS * S_STRIDE + JTILE * KV_STRIDE + QROWS * QS_STRIDE + 16) * 4;
    cudaFuncSetAttribute(fused_attn, cudaFuncAttributeMaxDynamicSharedMemorySize,
                         smem_bytes);
    dim3 gattn(SS / QROWS, HH, BB);
    fused_attn<<<gattn, 256, smem_bytes>>>(pQ, pK, pV, attn_dst, pCtx);

    // Output projection + bias
    dim3 gout(DD / 128, (BB * SS) / 128);
    out_proj<<<gout, 256>>>(pCtx, Wo, bo, out);
}

// round 4
// speedup vs baseline: 5.4704x; 1.1060x over previous
#include <cuda_runtime.h>
#include <math.h>

// Problem constants
#define BB 2
#define SS 2048
#define DD 768
#define HH 12
#define DK 64
#define QROWS 16
#define JTILE 256
#define S_STRIDE 2064      // padded row stride for score buffer (16B aligned)
#define KV_STRIDE 65       // padded row stride for K/V tiles (conflict-free)
#define QS_STRIDE 68       // padded row stride for Q tile (16B aligned)
#define ATHREADS 512

#define OUT_MAIN (2LL*2048*768)          // 3,145,728
#define ATTN_ELEMS (2LL*12*2048*2048)    // 100,663,296

// Scratch (static device arrays: allocation-free per harness rules)
__device__ float g_Q[(size_t)BB*SS*DD];
__device__ float g_K[(size_t)BB*SS*DD];
__device__ float g_V[(size_t)BB*SS*DD];
__device__ float g_ctx[(size_t)BB*SS*DD];
__device__ float g_attn[(size_t)ATTN_ELEMS];

// ---------------------------------------------------------------------------
// 128x128x8 SGEMM: C[M,N] = A[M,K] @ W[N,K]^T (+ optional bias).
// ---------------------------------------------------------------------------
__device__ __forceinline__ void gemm128_body(const float* __restrict__ A,
                                             const float* __restrict__ W,
                                             const float* __restrict__ bias,
                                             float* __restrict__ C,
                                             int M, int N, int K,
                                             int bm, int bn) {
    __shared__ float As[8][128];
    __shared__ float Ws[8][128];

    const int tid = threadIdx.x;
    const int tx = tid & 15;
    const int ty = tid >> 4;
    const int lrow = tid >> 1;          // 0..127
    const int lk   = (tid & 1) * 4;     // 0 or 4

    const float* Aptr = A + (size_t)(bm + lrow) * K + lk;
    const float* Wptr = W + (size_t)(bn + lrow) * K + lk;

    float acc[8][8];
#pragma unroll
    for (int i = 0; i < 8; i++)
#pragma unroll
        for (int j = 0; j < 8; j++) acc[i][j] = 0.f;

    float4 a4 = *(const float4*)(Aptr);
    float4 w4 = *(const float4*)(Wptr);

    for (int k0 = 0; k0 < K; k0 += 8) {
        As[lk+0][lrow] = a4.x; As[lk+1][lrow] = a4.y;
        As[lk+2][lrow] = a4.z; As[lk+3][lrow] = a4.w;
        Ws[lk+0][lrow] = w4.x; Ws[lk+1][lrow] = w4.y;
        Ws[lk+2][lrow] = w4.z; Ws[lk+3][lrow] = w4.w;
        __syncthreads();

        if (k0 + 8 < K) {
            a4 = *(const float4*)(Aptr + k0 + 8);
            w4 = *(const float4*)(Wptr + k0 + 8);
        }

#pragma unroll
        for (int kk = 0; kk < 8; kk++) {
            float ar[8], wr[8];
            *(float4*)(ar)     = *(const float4*)&As[kk][ty*8];
            *(float4*)(ar + 4) = *(const float4*)&As[kk][ty*8 + 4];
            *(float4*)(wr)     = *(const float4*)&Ws[kk][tx*8];
            *(float4*)(wr + 4) = *(const float4*)&Ws[kk][tx*8 + 4];
#pragma unroll
            for (int i = 0; i < 8; i++)
#pragma unroll
                for (int j = 0; j < 8; j++) acc[i][j] += ar[i] * wr[j];
        }
        __syncthreads();
    }

#pragma unroll
    for (int i = 0; i < 8; i++) {
        float* crow = C + (size_t)(bm + ty*8 + i) * N + bn + tx*8;
        float4 v0, v1;
        v0.x = acc[i][0]; v0.y = acc[i][1]; v0.z = acc[i][2]; v0.w = acc[i][3];
        v1.x = acc[i][4]; v1.y = acc[i][5]; v1.z = acc[i][6]; v1.w = acc[i][7];
        if (bias) {
            const float* bp = bias + bn + tx*8;
            v0.x += bp[0]; v0.y += bp[1]; v0.z += bp[2]; v0.w += bp[3];
            v1.x += bp[4]; v1.y += bp[5]; v1.z += bp[6]; v1.w += bp[7];
        }
        *(float4*)(crow)     = v0;
        *(float4*)(crow + 4) = v1;
    }
}

__global__ __launch_bounds__(256) void qkv_proj(
        const float* __restrict__ qin, const float* __restrict__ kin,
        const float* __restrict__ vin,
        const float* __restrict__ Wq, const float* __restrict__ Wk,
        const float* __restrict__ Wv,
        float* __restrict__ oq, float* __restrict__ ok, float* __restrict__ ov) {
    const float* A; const float* W; float* C;
    if (blockIdx.z == 0)      { A = qin; W = Wq; C = oq; }
    else if (blockIdx.z == 1) { A = kin; W = Wk; C = ok; }
    else                      { A = vin; W = Wv; C = ov; }
    gemm128_body(A, W, nullptr, C, BB*SS, DD, DD, blockIdx.y*128, blockIdx.x*128);
}

__global__ __launch_bounds__(256) void out_proj(
        const float* __restrict__ A, const float* __restrict__ W,
        const float* __restrict__ bias, float* __restrict__ C) {
    gemm128_body(A, W, bias, C, BB*SS, DD, DD, blockIdx.y*128, blockIdx.x*128);
}

// ---------------------------------------------------------------------------
// Fused attention, 512 threads/block.
// Block = (b, h, 16 q rows). Score strip 16 x <=2048 in SMEM (fp32).
//  Phase 1: QK^T, 256-wide j tiles, 4q x 2j per thread
//  Phase 2: row max/exp/sum (one warp per row)
//  Phase 3: float4 coalesced weight write
//  Phase 4: attn@V, 8-way split-j, 4q x 4d per thread, SMEM reduction.
// ---------------------------------------------------------------------------
__global__ __launch_bounds__(ATHREADS) void fused_attn(
        const float* __restrict__ Qp, const float* __restrict__ Kp,
        const float* __restrict__ Vp,
        float* __restrict__ attn, float* __restrict__ ctx) {
    const int qt = gridDim.x - 1 - blockIdx.x;   // biggest blocks first
    const int h  = blockIdx.y;
    const int b  = blockIdx.z;
    const int q0 = qt * QROWS;
    const int tid = threadIdx.x;

    extern __shared__ float sm[];
    float* s    = sm;                               // [16][S_STRIDE]
    float* kv   = sm + QROWS * S_STRIDE;            // [256][KV_STRIDE]
    float* qs   = kv + JTILE * KV_STRIDE;           // [16][QS_STRIDE]
    float* lrow = qs + QROWS * QS_STRIDE;           // [16]

    // Load Q tile (16 x 64)
    for (int l = tid; l < QROWS * 16; l += ATHREADS) {
        int r = l >> 4, k4 = (l & 15) * 4;
        float4 g = *(const float4*)(Qp +
            ((size_t)(b * SS + q0 + r)) * DD + h * DK + k4);
        float* dst = qs + r * QS_STRIDE + k4;
        dst[0] = g.x; dst[1] = g.y; dst[2] = g.z; dst[3] = g.w;
    }

    const int ntile = (q0 + QROWS + JTILE - 1) >> 8;
    const int jlim  = ntile * JTILE;

    // ---- Phase 1: scores (QK^T), 4q x 2j per thread ----
    {
        const int tq = tid >> 7;       // 0..3 -> rows tq*4 .. tq*4+3
        const int tj = tid & 127;      // j cols tj, tj+128
        for (int t = 0; t < ntile; t++) {
            const int j0 = t * JTILE;
            __syncthreads();
            for (int l = tid; l < JTILE * 16; l += ATHREADS) {
                int jr = l >> 4, k4 = (l & 15) * 4;
                float4 g = *(const float4*)(Kp +
                    ((size_t)(b * SS + j0 + jr)) * DD + h * DK + k4);
                float* dst = kv + jr * KV_STRIDE + k4;
                dst[0] = g.x; dst[1] = g.y; dst[2] = g.z; dst[3] = g.w;
            }
            __syncthreads();

            float acc[4][2];
#pragma unroll
            for (int i = 0; i < 4; i++) { acc[i][0] = 0.f; acc[i][1] = 0.f; }

#pragma unroll 4
            for (int k = 0; k < 64; k += 4) {
                float4 qv[4];
#pragma unroll
                for (int i = 0; i < 4; i++)
                    qv[i] = *(const float4*)&qs[(tq*4 + i) * QS_STRIDE + k];
#pragma unroll
                for (int m = 0; m < 2; m++) {
                    const float* kp = kv + (tj + 128*m) * KV_STRIDE + k;
                    float k0v = kp[0], k1v = kp[1], k2v = kp[2], k3v = kp[3];
#pragma unroll
                    for (int i = 0; i < 4; i++)
                        acc[i][m] += qv[i].x*k0v + qv[i].y*k1v +
                                     qv[i].z*k2v + qv[i].w*k3v;
                }
            }

#pragma unroll
            for (int m = 0; m < 2; m++) {
                const int gj = j0 + tj + 128*m;
#pragma unroll
                for (int i = 0; i < 4; i++) {
                    const int qrow = q0 + tq*4 + i;
                    s[(tq*4 + i) * S_STRIDE + gj] =
                        (gj <= qrow) ? acc[i][m] * 0.125f : -1e30f;
                }
            }
        }
    }
    __syncthreads();

    // ---- Phase 2: softmax stats (one warp per row) ----
    {
        const int r    = tid >> 5;     // 0..15
        const int lane = tid & 31;
        float* srow = s + r * S_STRIDE;
        float m = -1e30f;
        for (int j = lane; j < jlim; j += 32) m = fmaxf(m, srow[j]);
#pragma unroll
        for (int o = 16; o; o >>= 1)
            m = fmaxf(m, __shfl_xor_sync(0xffffffffu, m, o));
        float sum = 0.f;
        for (int j = lane; j < jlim; j += 32) {
            float e = __expf(srow[j] - m);
            srow[j] = e;
            sum += e;
        }
#pragma unroll
        for (int o = 16; o; o >>= 1)
            sum += __shfl_xor_sync(0xffffffffu, sum, o);
        if (lane == 0) lrow[r] = 1.0f / sum;
    }
    __syncthreads();

    // ---- Phase 3: write normalized weights once (float4) ----
    for (int r = 0; r < QROWS; r++) {
        const float inv = lrow[r];
        const float4* srow = (const float4*)(s + r * S_STRIDE);
        float4* arow = (float4*)(attn +
            (((size_t)(b * HH + h) * SS) + q0 + r) * SS);
        const int j4lim = jlim >> 2;
        for (int j = tid; j < j4lim; j += ATHREADS) {
            float4 v = srow[j];
            v.x *= inv; v.y *= inv; v.z *= inv; v.w *= inv;
            arow[j] = v;
        }
        const float4 z = {0.f, 0.f, 0.f, 0.f};
        for (int j = j4lim + tid; j < SS/4; j += ATHREADS) arow[j] = z;
    }

    // ---- Phase 4: attn @ V (8-way split-j, 4q x 4d per thread) ----
    {
        const int td  = tid & 15;         // d cols td + 16*m
        const int tq4 = (tid >> 4) & 3;   // q rows tq4*4 + i
        const int tj8 = tid >> 6;         // j slice tj8*32 .. +31

        float c[4][4];
#pragma unroll
        for (int i = 0; i < 4; i++)
#pragma unroll
            for (int m = 0; m < 4; m++) c[i][m] = 0.f;

        for (int t = 0; t < ntile; t++) {
            const int j0 = t * JTILE;
            __syncthreads();
            for (int l = tid; l < JTILE * 16; l += ATHREADS) {
                int jr = l >> 4, k4 = (l & 15) * 4;
                float4 g = *(const float4*)(Vp +
                    ((size_t)(b * SS + j0 + jr)) * DD + h * DK + k4);
                float* dst = kv + jr * KV_STRIDE + k4;
                dst[0] = g.x; dst[1] = g.y; dst[2] = g.z; dst[3] = g.w;
            }
            __syncthreads();

#pragma unroll 4
            for (int jj = 0; jj < 32; jj += 4) {
                const int j = tj8 * 32 + jj;
                float4 sv[4];
#pragma unroll
                for (int i = 0; i < 4; i++)
                    sv[i] = *(const float4*)&s[(tq4*4 + i) * S_STRIDE + j0 + j];
#pragma unroll
                for (int m = 0; m < 4; m++) {
                    const int d = td + 16*m;
                    float v0 = kv[(j+0) * KV_STRIDE + d];
                    float v1 = kv[(j+1) * KV_STRIDE + d];
                    float v2 = kv[(j+2) * KV_STRIDE + d];
                    float v3 = kv[(j+3) * KV_STRIDE + d];
#pragma unroll
                    for (int i = 0; i < 4; i++)
                        c[i][m] += sv[i].x*v0 + sv[i].y*v1 +
                                   sv[i].z*v2 + sv[i].w*v3;
                }
            }
        }

        // reduce across the 8 j-slices via SMEM (reuse score buffer)
        __syncthreads();
        float* red = s;   // [8][16][64]
#pragma unroll
        for (int i = 0; i < 4; i++)
#pragma unroll
            for (int m = 0; m < 4; m++)
                red[tj8 * 1024 + (tq4*4 + i) * 64 + td + 16*m] = c[i][m];
        __syncthreads();

        for (int l = tid; l < 1024; l += ATHREADS) {
            const int q = l >> 6, d = l & 63;
            float v = 0.f;
#pragma unroll
            for (int p = 0; p < 8; p++) v += red[p * 1024 + l];
            ctx[((size_t)(b * SS + q0 + q)) * DD + h * DK + d] = v * lrow[q];
        }
    }
}

// ---------------------------------------------------------------------------
extern "C" void kernel_launch(void* const* d_in, const int* in_sizes, int n_in,
                              void* d_out, int out_size) {
    const float* q_in = (const float*)d_in[0];
    const float* k_in = (const float*)d_in[1];
    const float* v_in = (const float*)d_in[2];
    // d_in[3] = mask (int32) — causal, known statically, ignored
    const float* Wq = (const float*)d_in[4];
    const float* Wk = (const float*)d_in[5];
    const float* Wv = (const float*)d_in[6];
    const float* Wo = (const float*)d_in[7];
    const float* bo = (const float*)d_in[8];

    float* out = (float*)d_out;
    float* attn_dst;
    if ((long long)out_size >= OUT_MAIN + ATTN_ELEMS) {
        attn_dst = out + OUT_MAIN;
    } else {
        cudaGetSymbolAddress((void**)&attn_dst, g_attn);
    }

    float *pQ, *pK, *pV, *pCtx;
    cudaGetSymbolAddress((void**)&pQ,   g_Q);
    cudaGetSymbolAddress((void**)&pK,   g_K);
    cudaGetSymbolAddress((void**)&pV,   g_V);
    cudaGetSymbolAddress((void**)&pCtx, g_ctx);

    // Fused QKV projections
    dim3 gqkv(DD / 128, (BB * SS) / 128, 3);
    qkv_proj<<<gqkv, 256>>>(q_in, k_in, v_in, Wq, Wk, Wv, pQ, pK, pV);

    // Fused attention
    const int smem_bytes =
        (QROWS * S_STRIDE + JTILE * KV_STRIDE + QROWS * QS_STRIDE + 16) * 4;
    cudaFuncSetAttribute(fused_attn, cudaFuncAttributeMaxDynamicSharedMemorySize,
                         smem_bytes);
    dim3 gattn(SS / QROWS, HH, BB);
    fused_attn<<<gattn, ATHREADS, smem_bytes>>>(pQ, pK, pV, attn_dst, pCtx);

    // Output projection + bias
    dim3 gout(DD / 128, (BB * SS) / 128);
    out_proj<<<gout, 256>>>(pCtx, Wo, bo, out);
}

// round 6
// speedup vs baseline: 6.8508x; 1.2523x over previous
#include <cuda_runtime.h>
#include <cuda_bf16.h>
#include <math.h>
#include <stdint.h>

// Problem constants
#define BB 2
#define SS 2048
#define DD 768
#define HH 12
#define DK 64
#define QROWS 16
#define JTILE 256
#define S_STRIDE 2064
#define KV_STRIDE 65
#define QS_STRIDE 68
#define ATHREADS 512

#define OUT_MAIN (2LL*2048*768)
#define ATTN_ELEMS (2LL*12*2048*2048)

#define MROWS (BB*SS)            // 4096
#define ASEG ((size_t)MROWS*DD)  // 3145728
#define WSEG ((size_t)DD*DD)     // 589824

// fp32 scratch
__device__ float g_Q[(size_t)BB*SS*DD];
__device__ float g_K[(size_t)BB*SS*DD];
__device__ float g_V[(size_t)BB*SS*DD];
__device__ float g_ctx[(size_t)BB*SS*DD];
__device__ float g_attn[(size_t)ATTN_ELEMS];
// bf16 split scratch
__device__ __nv_bfloat16 g_Ahi[3*ASEG];
__device__ __nv_bfloat16 g_Alo[3*ASEG];
__device__ __nv_bfloat16 g_Whi[4*WSEG];
__device__ __nv_bfloat16 g_Wlo[4*WSEG];
__device__ __nv_bfloat16 g_Chi[ASEG];
__device__ __nv_bfloat16 g_Clo[ASEG];

// ===================== fp32 -> bf16 hi/lo split ============================
__global__ void cvt3(const float* __restrict__ x0, const float* __restrict__ x1,
                     const float* __restrict__ x2,
                     __nv_bfloat16* __restrict__ hi, __nv_bfloat16* __restrict__ lo,
                     int n4) {
    const float* x = blockIdx.z == 0 ? x0 : (blockIdx.z == 1 ? x1 : x2);
    size_t base = (size_t)blockIdx.z * (size_t)n4 * 4;
    int i = blockIdx.x * blockDim.x + threadIdx.x;
    if (i >= n4) return;
    float4 v = ((const float4*)x)[i];
    __nv_bfloat162 h01 = __floats2bfloat162_rn(v.x, v.y);
    __nv_bfloat162 h23 = __floats2bfloat162_rn(v.z, v.w);
    float lx = v.x - __bfloat162float(__low2bfloat16(h01));
    float ly = v.y - __bfloat162float(__high2bfloat16(h01));
    float lz = v.z - __bfloat162float(__low2bfloat16(h23));
    float lw = v.w - __bfloat162float(__high2bfloat16(h23));
    ((__nv_bfloat162*)(hi + base))[i*2]     = h01;
    ((__nv_bfloat162*)(hi + base))[i*2 + 1] = h23;
    ((__nv_bfloat162*)(lo + base))[i*2]     = __floats2bfloat162_rn(lx, ly);
    ((__nv_bfloat162*)(lo + base))[i*2 + 1] = __floats2bfloat162_rn(lz, lw);
}

__global__ void cvt4(const float* __restrict__ x0, const float* __restrict__ x1,
                     const float* __restrict__ x2, const float* __restrict__ x3,
                     __nv_bfloat16* __restrict__ hi, __nv_bfloat16* __restrict__ lo,
                     int n4) {
    const float* xs[4] = {x0, x1, x2, x3};
    const float* x = xs[blockIdx.z];
    size_t base = (size_t)blockIdx.z * (size_t)n4 * 4;
    int i = blockIdx.x * blockDim.x + threadIdx.x;
    if (i >= n4) return;
    float4 v = ((const float4*)x)[i];
    __nv_bfloat162 h01 = __floats2bfloat162_rn(v.x, v.y);
    __nv_bfloat162 h23 = __floats2bfloat162_rn(v.z, v.w);
    float lx = v.x - __bfloat162float(__low2bfloat16(h01));
    float ly = v.y - __bfloat162float(__high2bfloat16(h01));
    float lz = v.z - __bfloat162float(__low2bfloat16(h23));
    float lw = v.w - __bfloat162float(__high2bfloat16(h23));
    ((__nv_bfloat162*)(hi + base))[i*2]     = h01;
    ((__nv_bfloat162*)(hi + base))[i*2 + 1] = h23;
    ((__nv_bfloat162*)(lo + base))[i*2]     = __floats2bfloat162_rn(lx, ly);
    ((__nv_bfloat162*)(lo + base))[i*2 + 1] = __floats2bfloat162_rn(lz, lw);
}

// ===================== mma.sync split-bf16 GEMM =============================
// C[M,768] = A[M,768] @ W[768,768]^T (+bias).
// A,W as bf16 hi/lo pairs; 3 fp32-accumulated products (hh, hl, lh).
// CTA: 256 threads, 128x128 tile; warp = 32x64 (2 x 8 m16n8k16 frags).
#define TST 40   // smem row stride in bf16 (20 words -> conflict-free frags)

__device__ __forceinline__ void mma_bf16(float* c, const uint32_t* a,
                                         uint32_t b0, uint32_t b1) {
    asm volatile(
        "mma.sync.aligned.m16n8k16.row.col.f32.bf16.bf16.f32 "
        "{%0,%1,%2,%3}, {%4,%5,%6,%7}, {%8,%9}, {%0,%1,%2,%3};"
        : "+f"(c[0]), "+f"(c[1]), "+f"(c[2]), "+f"(c[3])
        : "r"(a[0]), "r"(a[1]), "r"(a[2]), "r"(a[3]), "r"(b0), "r"(b1));
}

__global__ __launch_bounds__(256) void gemm_mma(
        const __nv_bfloat16* __restrict__ Ahi, const __nv_bfloat16* __restrict__ Alo,
        const __nv_bfloat16* __restrict__ Whi, const __nv_bfloat16* __restrict__ Wlo,
        const float* __restrict__ bias,
        float* C0, float* C1, float* C2) {
    __shared__ __nv_bfloat16 sAh[128*TST], sAl[128*TST];
    __shared__ __nv_bfloat16 sWh[128*TST], sWl[128*TST];

    const int tid  = threadIdx.x;
    const int lane = tid & 31;
    const int wid  = tid >> 5;
    const int wm   = wid >> 1;          // 0..3
    const int wn   = wid & 1;           // 0..1
    const int g    = lane >> 2;         // 0..7
    const int tg   = lane & 3;          // 0..3
    const int z    = blockIdx.z;

    const __nv_bfloat16* Ah = Ahi + (size_t)z * ASEG;
    const __nv_bfloat16* Al = Alo + (size_t)z * ASEG;
    const __nv_bfloat16* Wh = Whi + (size_t)z * WSEG;
    const __nv_bfloat16* Wl = Wlo + (size_t)z * WSEG;
    float* C = (z == 0) ? C0 : (z == 1) ? C1 : C2;

    const int bm = blockIdx.y * 128;
    const int bn = blockIdx.x * 128;

    // loader coords: 128 rows x 32 cols bf16, 2 chunks of 8 per thread
    const int lr = tid >> 2;            // 0..63 (and +64)
    const int lc = (tid & 3) * 8;       // 0,8,16,24

    const __nv_bfloat16* gAh0 = Ah + (size_t)(bm + lr)      * DD + lc;
    const __nv_bfloat16* gAh1 = Ah + (size_t)(bm + lr + 64) * DD + lc;
    const __nv_bfloat16* gAl0 = Al + (size_t)(bm + lr)      * DD + lc;
    const __nv_bfloat16* gAl1 = Al + (size_t)(bm + lr + 64) * DD + lc;
    const __nv_bfloat16* gWh0 = Wh + (size_t)(bn + lr)      * DD + lc;
    const __nv_bfloat16* gWh1 = Wh + (size_t)(bn + lr + 64) * DD + lc;
    const __nv_bfloat16* gWl0 = Wl + (size_t)(bn + lr)      * DD + lc;
    const __nv_bfloat16* gWl1 = Wl + (size_t)(bn + lr + 64) * DD + lc;

    float acc[2][8][4];
#pragma unroll
    for (int mi = 0; mi < 2; mi++)
#pragma unroll
        for (int ni = 0; ni < 8; ni++)
#pragma unroll
            for (int r = 0; r < 4; r++) acc[mi][ni][r] = 0.f;

    uint4 p[8];
    p[0] = *(const uint4*)(gAh0); p[1] = *(const uint4*)(gAh1);
    p[2] = *(const uint4*)(gAl0); p[3] = *(const uint4*)(gAl1);
    p[4] = *(const uint4*)(gWh0); p[5] = *(const uint4*)(gWh1);
    p[6] = *(const uint4*)(gWl0); p[7] = *(const uint4*)(gWl1);

    for (int k0 = 0; k0 < DD; k0 += 32) {
        *(uint4*)(sAh + lr*TST + lc)        = p[0];
        *(uint4*)(sAh + (lr+64)*TST + lc)   = p[1];
        *(uint4*)(sAl + lr*TST + lc)        = p[2];
        *(uint4*)(sAl + (lr+64)*TST + lc)   = p[3];
        *(uint4*)(sWh + lr*TST + lc)        = p[4];
        *(uint4*)(sWh + (lr+64)*TST + lc)   = p[5];
        *(uint4*)(sWl + lr*TST + lc)        = p[6];
        *(uint4*)(sWl + (lr+64)*TST + lc)   = p[7];
        __syncthreads();

        if (k0 + 32 < DD) {
            const int kn = k0 + 32;
            p[0] = *(const uint4*)(gAh0 + kn); p[1] = *(const uint4*)(gAh1 + kn);
            p[2] = *(const uint4*)(gAl0 + kn); p[3] = *(const uint4*)(gAl1 + kn);
            p[4] = *(const uint4*)(gWh0 + kn); p[5] = *(const uint4*)(gWh1 + kn);
            p[6] = *(const uint4*)(gWl0 + kn); p[7] = *(const uint4*)(gWl1 + kn);
        }

#pragma unroll
        for (int kk = 0; kk < 32; kk += 16) {
            // A fragments (hi, lo) for the 2 m16 tiles
            uint32_t ah[2][4], al[2][4];
#pragma unroll
            for (int mi = 0; mi < 2; mi++) {
                const int ar = wm*32 + mi*16;
                ah[mi][0] = *(const uint32_t*)(sAh + (ar+g)   * TST + kk + tg*2);
                ah[mi][1] = *(const uint32_t*)(sAh + (ar+g+8) * TST + kk + tg*2);
                ah[mi][2] = *(const uint32_t*)(sAh + (ar+g)   * TST + kk + tg*2 + 8);
                ah[mi][3] = *(const uint32_t*)(sAh + (ar+g+8) * TST + kk + tg*2 + 8);
                al[mi][0] = *(const uint32_t*)(sAl + (ar+g)   * TST + kk + tg*2);
                al[mi][1] = *(const uint32_t*)(sAl + (ar+g+8) * TST + kk + tg*2);
                al[mi][2] = *(const uint32_t*)(sAl + (ar+g)   * TST + kk + tg*2 + 8);
                al[mi][3] = *(const uint32_t*)(sAl + (ar+g+8) * TST + kk + tg*2 + 8);
            }
            // B fragments for 8 n8 tiles
            uint32_t bh[8][2], bl[8][2];
#pragma unroll
            for (int ni = 0; ni < 8; ni++) {
                const int nr = wn*64 + ni*8 + g;
                bh[ni][0] = *(const uint32_t*)(sWh + nr * TST + kk + tg*2);
                bh[ni][1] = *(const uint32_t*)(sWh + nr * TST + kk + tg*2 + 8);
                bl[ni][0] = *(const uint32_t*)(sWl + nr * TST + kk + tg*2);
                bl[ni][1] = *(const uint32_t*)(sWl + nr * TST + kk + tg*2 + 8);
            }
            // hh product
#pragma unroll
            for (int ni = 0; ni < 8; ni++)
#pragma unroll
                for (int mi = 0; mi < 2; mi++)
                    mma_bf16(acc[mi][ni], ah[mi], bh[ni][0], bh[ni][1]);
            // hl product
#pragma unroll
            for (int ni = 0; ni < 8; ni++)
#pragma unroll
                for (int mi = 0; mi < 2; mi++)
                    mma_bf16(acc[mi][ni], ah[mi], bl[ni][0], bl[ni][1]);
            // lh product
#pragma unroll
            for (int ni = 0; ni < 8; ni++)
#pragma unroll
                for (int mi = 0; mi < 2; mi++)
                    mma_bf16(acc[mi][ni], al[mi], bh[ni][0], bh[ni][1]);
        }
        __syncthreads();
    }

    // epilogue
#pragma unroll
    for (int mi = 0; mi < 2; mi++) {
        const int row0 = bm + wm*32 + mi*16 + g;
#pragma unroll
        for (int ni = 0; ni < 8; ni++) {
            const int col = bn + wn*64 + ni*8 + tg*2;
            float b0v = 0.f, b1v = 0.f;
            if (bias) { b0v = bias[col]; b1v = bias[col+1]; }
            float2 v0 = {acc[mi][ni][0] + b0v, acc[mi][ni][1] + b1v};
            float2 v1 = {acc[mi][ni][2] + b0v, acc[mi][ni][3] + b1v};
            *(float2*)(C + (size_t)row0 * DD + col)       = v0;
            *(float2*)(C + (size_t)(row0+8) * DD + col)   = v1;
        }
    }
}

// ===================== fused attention (unchanged, proven) =================
__global__ __launch_bounds__(ATHREADS) void fused_attn(
        const float* __restrict__ Qp, const float* __restrict__ Kp,
        const float* __restrict__ Vp,
        float* __restrict__ attn, float* __restrict__ ctx) {
    const int qt = gridDim.x - 1 - blockIdx.x;
    const int h  = blockIdx.y;
    const int b  = blockIdx.z;
    const int q0 = qt * QROWS;
    const int tid = threadIdx.x;

    extern __shared__ float sm[];
    float* s    = sm;
    float* kv   = sm + QROWS * S_STRIDE;
    float* qs   = kv + JTILE * KV_STRIDE;
    float* lrow = qs + QROWS * QS_STRIDE;

    for (int l = tid; l < QROWS * 16; l += ATHREADS) {
        int r = l >> 4, k4 = (l & 15) * 4;
        float4 g = *(const float4*)(Qp +
            ((size_t)(b * SS + q0 + r)) * DD + h * DK + k4);
        float* dst = qs + r * QS_STRIDE + k4;
        dst[0] = g.x; dst[1] = g.y; dst[2] = g.z; dst[3] = g.w;
    }

    const int ntile = (q0 + QROWS + JTILE - 1) >> 8;
    const int jlim  = ntile * JTILE;

    {
        const int tq = tid >> 7;
        const int tj = tid & 127;
        for (int t = 0; t < ntile; t++) {
            const int j0 = t * JTILE;
            __syncthreads();
            for (int l = tid; l < JTILE * 16; l += ATHREADS) {
                int jr = l >> 4, k4 = (l & 15) * 4;
                float4 g = *(const float4*)(Kp +
                    ((size_t)(b * SS + j0 + jr)) * DD + h * DK + k4);
                float* dst = kv + jr * KV_STRIDE + k4;
                dst[0] = g.x; dst[1] = g.y; dst[2] = g.z; dst[3] = g.w;
            }
            __syncthreads();

            float acc[4][2];
#pragma unroll
            for (int i = 0; i < 4; i++) { acc[i][0] = 0.f; acc[i][1] = 0.f; }

#pragma unroll 4
            for (int k = 0; k < 64; k += 4) {
                float4 qv[4];
#pragma unroll
                for (int i = 0; i < 4; i++)
                    qv[i] = *(const float4*)&qs[(tq*4 + i) * QS_STRIDE + k];
#pragma unroll
                for (int m = 0; m < 2; m++) {
                    const float* kp = kv + (tj + 128*m) * KV_STRIDE + k;
                    float k0v = kp[0], k1v = kp[1], k2v = kp[2], k3v = kp[3];
#pragma unroll
                    for (int i = 0; i < 4; i++)
                        acc[i][m] += qv[i].x*k0v + qv[i].y*k1v +
                                     qv[i].z*k2v + qv[i].w*k3v;
                }
            }

#pragma unroll
            for (int m = 0; m < 2; m++) {
                const int gj = j0 + tj + 128*m;
#pragma unroll
                for (int i = 0; i < 4; i++) {
                    const int qrow = q0 + tq*4 + i;
                    s[(tq*4 + i) * S_STRIDE + gj] =
                        (gj <= qrow) ? acc[i][m] * 0.125f : -1e30f;
                }
            }
        }
    }
    __syncthreads();

    {
        const int r    = tid >> 5;
        const int lane = tid & 31;
        float* srow = s + r * S_STRIDE;
        float m = -1e30f;
        for (int j = lane; j < jlim; j += 32) m = fmaxf(m, srow[j]);
#pragma unroll
        for (int o = 16; o; o >>= 1)
            m = fmaxf(m, __shfl_xor_sync(0xffffffffu, m, o));
        float sum = 0.f;
        for (int j = lane; j < jlim; j += 32) {
            float e = __expf(srow[j] - m);
            srow[j] = e;
            sum += e;
        }
#pragma unroll
        for (int o = 16; o; o >>= 1)
            sum += __shfl_xor_sync(0xffffffffu, sum, o);
        if (lane == 0) lrow[r] = 1.0f / sum;
    }
    __syncthreads();

    for (int r = 0; r < QROWS; r++) {
        const float inv = lrow[r];
        const float4* srow = (const float4*)(s + r * S_STRIDE);
        float4* arow = (float4*)(attn +
            (((size_t)(b * HH + h) * SS) + q0 + r) * SS);
        const int j4lim = jlim >> 2;
        for (int j = tid; j < j4lim; j += ATHREADS) {
            float4 v = srow[j];
            v.x *= inv; v.y *= inv; v.z *= inv; v.w *= inv;
            arow[j] = v;
        }
        const float4 zz = {0.f, 0.f, 0.f, 0.f};
        for (int j = j4lim + tid; j < SS/4; j += ATHREADS) arow[j] = zz;
    }

    {
        const int td  = tid & 15;
        const int tq4 = (tid >> 4) & 3;
        const int tj8 = tid >> 6;

        float c[4][4];
#pragma unroll
        for (int i = 0; i < 4; i++)
#pragma unroll
            for (int m = 0; m < 4; m++) c[i][m] = 0.f;

        for (int t = 0; t < ntile; t++) {
            const int j0 = t * JTILE;
            __syncthreads();
            for (int l = tid; l < JTILE * 16; l += ATHREADS) {
                int jr = l >> 4, k4 = (l & 15) * 4;
                float4 g = *(const float4*)(Vp +
                    ((size_t)(b * SS + j0 + jr)) * DD + h * DK + k4);
                float* dst = kv + jr * KV_STRIDE + k4;
                dst[0] = g.x; dst[1] = g.y; dst[2] = g.z; dst[3] = g.w;
            }
            __syncthreads();

#pragma unroll 4
            for (int jj = 0; jj < 32; jj += 4) {
                const int j = tj8 * 32 + jj;
                float4 sv[4];
#pragma unroll
                for (int i = 0; i < 4; i++)
                    sv[i] = *(const float4*)&s[(tq4*4 + i) * S_STRIDE + j0 + j];
#pragma unroll
                for (int m = 0; m < 4; m++) {
                    const int d = td + 16*m;
                    float v0 = kv[(j+0) * KV_STRIDE + d];
                    float v1 = kv[(j+1) * KV_STRIDE + d];
                    float v2 = kv[(j+2) * KV_STRIDE + d];
                    float v3 = kv[(j+3) * KV_STRIDE + d];
#pragma unroll
                    for (int i = 0; i < 4; i++)
                        c[i][m] += sv[i].x*v0 + sv[i].y*v1 +
                                   sv[i].z*v2 + sv[i].w*v3;
                }
            }
        }

        __syncthreads();
        float* red = s;
#pragma unroll
        for (int i = 0; i < 4; i++)
#pragma unroll
            for (int m = 0; m < 4; m++)
                red[tj8 * 1024 + (tq4*4 + i) * 64 + td + 16*m] = c[i][m];
        __syncthreads();

        for (int l = tid; l < 1024; l += ATHREADS) {
            const int q = l >> 6, d = l & 63;
            float v = 0.f;
#pragma unroll
            for (int p = 0; p < 8; p++) v += red[p * 1024 + l];
            ctx[((size_t)(b * SS + q0 + q)) * DD + h * DK + d] = v * lrow[q];
        }
    }
}

// ---------------------------------------------------------------------------
extern "C" void kernel_launch(void* const* d_in, const int* in_sizes, int n_in,
                              void* d_out, int out_size) {
    const float* q_in = (const float*)d_in[0];
    const float* k_in = (const float*)d_in[1];
    const float* v_in = (const float*)d_in[2];
    const float* Wq = (const float*)d_in[4];
    const float* Wk = (const float*)d_in[5];
    const float* Wv = (const float*)d_in[6];
    const float* Wo = (const float*)d_in[7];
    const float* bo = (const float*)d_in[8];

    float* out = (float*)d_out;
    float* attn_dst;
    if ((long long)out_size >= OUT_MAIN + ATTN_ELEMS) {
        attn_dst = out + OUT_MAIN;
    } else {
        cudaGetSymbolAddress((void**)&attn_dst, g_attn);
    }

    float *pQ, *pK, *pV, *pCtx;
    cudaGetSymbolAddress((void**)&pQ,   g_Q);
    cudaGetSymbolAddress((void**)&pK,   g_K);
    cudaGetSymbolAddress((void**)&pV,   g_V);
    cudaGetSymbolAddress((void**)&pCtx, g_ctx);
    __nv_bfloat16 *pAhi, *pAlo, *pWhi, *pWlo, *pChi, *pClo;
    cudaGetSymbolAddress((void**)&pAhi, g_Ahi);
    cudaGetSymbolAddress((void**)&pAlo, g_Alo);
    cudaGetSymbolAddress((void**)&pWhi, g_Whi);
    cudaGetSymbolAddress((void**)&pWlo, g_Wlo);
    cudaGetSymbolAddress((void**)&pChi, g_Chi);
    cudaGetSymbolAddress((void**)&pClo, g_Clo);

    // split inputs + weights to bf16 hi/lo
    {
        int n4 = (int)(ASEG / 4);
        dim3 g((n4 + 255) / 256, 1, 3);
        cvt3<<<g, 256>>>(q_in, k_in, v_in, pAhi, pAlo, n4);
        int w4 = (int)(WSEG / 4);
        dim3 gw((w4 + 255) / 256, 1, 4);
        cvt4<<<gw, 256>>>(Wq, Wk, Wv, Wo, pWhi, pWlo, w4);
    }

    // QKV projections on tensor cores (mma.sync)
    {
        dim3 g(DD / 128, MROWS / 128, 3);
        gemm_mma<<<g, 256>>>(pAhi, pAlo, pWhi, pWlo, nullptr, pQ, pK, pV);
    }

    // fused attention
    {
        const int smem_bytes =
            (QROWS * S_STRIDE + JTILE * KV_STRIDE + QROWS * QS_STRIDE + 16) * 4;
        cudaFuncSetAttribute(fused_attn,
                             cudaFuncAttributeMaxDynamicSharedMemorySize, smem_bytes);
        dim3 g(SS / QROWS, HH, BB);
        fused_attn<<<g, ATHREADS, smem_bytes>>>(pQ, pK, pV, attn_dst, pCtx);
    }

    // split ctx, output projection
    {
        int n4 = (int)(ASEG / 4);
        dim3 g((n4 + 255) / 256, 1, 1);
        cvt3<<<g, 256>>>(pCtx, pCtx, pCtx, pChi, pClo, n4);
        dim3 gg(DD / 128, MROWS / 128, 1);
        gemm_mma<<<gg, 256>>>(pChi, pClo, pWhi + 3*WSEG, pWlo + 3*WSEG,
                              bo, out, out, out);
    }
}